// round 10
// baseline (speedup 1.0000x reference)
#include <cuda_runtime.h>
#include <cuda_bf16.h>

// Varifold loss on GB300 — factored Gaussian, packed-j f32x2, minimal padding (NFP=9984), g-trick.
// loss = (1/B) * sum_b [ K(s,s) + K(t,t) - 2 K(s,t) ]
// Factorization:
//   M' = sqrt(L) * Nn * exp(-|c'|^2 / 2)   with c' = C / sigma
//   cs = c' * sqrt(log2(e))                so pc = <cs_i,cs_j>
//   g  = <M'_i,M'_j> * 2^pc ;  term_ij = g^2   (exact: g^2 = dm^2 * e^{2<c'_i,c'_j>})

#define NV_CONST 5023
#define TI 384           // i-points per block (128 threads x 3)
#define TJ 384           // j-points per smem tile
#define BLOCK 128
#define NI 3
#define NFP_MAX 9984     // 26 * 384 — only 8 rows of padding over NF=9976
#define SMAX 8
#define PART_MAX 16384

__device__ float4 g_A[SMAX * NFP_MAX];   // (cs.x, cs.y, cs.z, M'.x)
__device__ float4 g_Bv[SMAX * NFP_MAX];  // (M'.y, M'.z, 0, 0)
__device__ double g_part[PART_MAX];

typedef unsigned long long ull;

__device__ __forceinline__ ull pk(float a, float b) {
    ull r; asm("mov.b64 %0, {%1,%2};" : "=l"(r) : "f"(a), "f"(b)); return r;
}
__device__ __forceinline__ void upk(ull v, float& a, float& b) {
    asm("mov.b64 {%0,%1}, %2;" : "=f"(a), "=f"(b) : "l"(v));
}
__device__ __forceinline__ ull f2mul(ull a, ull b) {
    ull r; asm("mul.rn.f32x2 %0, %1, %2;" : "=l"(r) : "l"(a), "l"(b)); return r;
}
__device__ __forceinline__ ull f2fma(ull a, ull b, ull c) {
    ull r; asm("fma.rn.f32x2 %0, %1, %2, %3;" : "=l"(r) : "l"(a), "l"(b), "l"(c)); return r;
}
__device__ __forceinline__ float ex2(float x) {
    float r; asm("ex2.approx.f32 %0, %1;" : "=f"(r) : "f"(x)); return r;
}

__global__ void prep_kernel(const float* __restrict__ pred,
                            const float* __restrict__ targ,
                            const int* __restrict__ faces,
                            int B, int NV, int NF, int NFP)
{
    int idx = blockIdx.x * blockDim.x + threadIdx.x;
    int total = 2 * B * NFP;
    if (idx >= total) return;
    int s = idx / NFP;
    int f = idx - s * NFP;

    float4 A = make_float4(0.f, 0.f, 0.f, 0.f);
    float4 Bv = make_float4(0.f, 0.f, 0.f, 0.f);

    if (f < NF) {
        const float* src = (s < B) ? pred : targ;
        int b = (s < B) ? s : (s - B);
        const float* base = src + (size_t)b * NV * 3;

        int i0 = faces[3 * f + 0];
        int i1 = faces[3 * f + 1];
        int i2 = faces[3 * f + 2];

        float x0 = base[3 * i0 + 0], y0 = base[3 * i0 + 1], z0 = base[3 * i0 + 2];
        float x1 = base[3 * i1 + 0], y1 = base[3 * i1 + 1], z1 = base[3 * i1 + 2];
        float x2 = base[3 * i2 + 0], y2 = base[3 * i2 + 1], z2 = base[3 * i2 + 2];

        // c' = centroid / sigma  (sigma = 0.03)
        const float SG = 33.333333333333336f;
        float cx = (x0 + x1 + x2) * (1.0f / 3.0f) * SG;
        float cy = (y0 + y1 + y2) * (1.0f / 3.0f) * SG;
        float cz = (z0 + z1 + z2) * (1.0f / 3.0f) * SG;

        float e1x = x1 - x0, e1y = y1 - y0, e1z = z1 - z0;
        float e2x = x2 - x0, e2y = y2 - y0, e2z = z2 - z0;

        float nx = 0.5f * (e1y * e2z - e1z * e2y);
        float ny = 0.5f * (e1z * e2x - e1x * e2z);
        float nz = 0.5f * (e1x * e2y - e1y * e2x);

        float L = sqrtf(nx * nx + ny * ny + nz * nz);
        float w = expf(-0.5f * (cx * cx + cy * cy + cz * cz));
        float sc = (sqrtf(L) / fmaxf(L, 1e-12f)) * w;
        float mx = nx * sc, my = ny * sc, mz = nz * sc;

        const float SQLE = 1.2011224087864498f;  // sqrt(log2(e))
        A = make_float4(cx * SQLE, cy * SQLE, cz * SQLE, mx);
        Bv = make_float4(my, mz, 0.f, 0.f);
    }
    g_A[(size_t)s * NFP + f] = A;
    g_Bv[(size_t)s * NFP + f] = Bv;
}

__global__ void __launch_bounds__(BLOCK, 6)
pair_kernel(int B, int NFP, int gx, int gy)
{
    // SoA j-tile: packed pairs of consecutive j-points load as one ld.shared.b64.
    __shared__ float s_x[TJ], s_y[TJ], s_z[TJ];
    __shared__ float s_mx[TJ], s_my[TJ], s_mz[TJ];
    __shared__ float red[BLOCK / 32];

    int z = blockIdx.z;
    int b = z / 3;
    int t = z - 3 * b;           // 0: ss, 1: tt, 2: st
    int pidx = (z * gy + blockIdx.y) * gx + blockIdx.x;

    float wgt = (t == 2) ? -2.f : 1.f;
    if (t < 2) {
        // symmetric kernel, TI == TJ: square tiles, strict triangle
        int jt = blockIdx.y, it = blockIdx.x;
        if (jt < it) {                    // strictly lower: skip
            if (threadIdx.x == 0) g_part[pidx] = 0.0;
            return;
        }
        if (jt > it) wgt = 2.f;           // strictly upper: count twice
    }

    int sx = (t == 1) ? (B + b) : b;
    int sy = (t == 0) ? b : (B + b);

    const float4* __restrict__ XA = g_A  + (size_t)sx * NFP;
    const float4* __restrict__ XB = g_Bv + (size_t)sx * NFP;
    const float4* __restrict__ YA = g_A  + (size_t)sy * NFP;
    const float4* __restrict__ YB = g_Bv + (size_t)sy * NFP;

    // Load NI i-points, duplicate each component {v,v} ONCE (hoisted out of j-loop)
    int i0 = blockIdx.x * TI + threadIdx.x;
    ull icx[NI], icy[NI], icz[NI], imx[NI], imy[NI], imz[NI];
#pragma unroll
    for (int k = 0; k < NI; k++) {
        float4 a = XA[i0 + k * BLOCK];
        float4 v = XB[i0 + k * BLOCK];
        icx[k] = pk(a.x, a.x);
        icy[k] = pk(a.y, a.y);
        icz[k] = pk(a.z, a.z);
        imx[k] = pk(a.w, a.w);
        imy[k] = pk(v.x, v.x);
        imz[k] = pk(v.y, v.y);
    }

    int j0 = blockIdx.y * TJ;
#pragma unroll
    for (int r = 0; r < TJ / BLOCK; r++) {
        int jj = threadIdx.x + r * BLOCK;
        float4 a = YA[j0 + jj];
        float4 v = YB[j0 + jj];
        s_x[jj] = a.x;  s_y[jj] = a.y;  s_z[jj] = a.z;
        s_mx[jj] = a.w; s_my[jj] = v.x; s_mz[jj] = v.y;
    }
    __syncthreads();

    const ull* __restrict__ px  = (const ull*)s_x;
    const ull* __restrict__ py  = (const ull*)s_y;
    const ull* __restrict__ pz  = (const ull*)s_z;
    const ull* __restrict__ pmx = (const ull*)s_mx;
    const ull* __restrict__ pmy = (const ull*)s_my;
    const ull* __restrict__ pmz = (const ull*)s_mz;

    ull acc[NI];
#pragma unroll
    for (int k = 0; k < NI; k++) acc[k] = 0ull;   // (0.0f, 0.0f)

#pragma unroll 4
    for (int j2 = 0; j2 < TJ / 2; j2++) {
        ull jx  = px[j2];
        ull jy  = py[j2];
        ull jz  = pz[j2];
        ull jmx = pmx[j2];
        ull jmy = pmy[j2];
        ull jmz = pmz[j2];
#pragma unroll
        for (int k = 0; k < NI; k++) {
            ull pc = f2fma(jz, icz[k], f2fma(jy, icy[k], f2mul(jx, icx[k])));
            ull dm = f2fma(jmz, imz[k], f2fma(jmy, imy[k], f2mul(jmx, imx[k])));
            float p0, p1; upk(pc, p0, p1);
            float e0 = ex2(p0);
            float e1 = ex2(p1);
            ull g = f2mul(dm, pk(e0, e1));   // rt2
            acc[k] = f2fma(g, g, acc[k]);    // rt2 (even/odd operand dedup)
        }
    }

    float tsum = 0.f;
#pragma unroll
    for (int k = 0; k < NI; k++) {
        float a0, a1; upk(acc[k], a0, a1);
        tsum += a0 + a1;
    }
    // warp shuffle reduction, then cross-warp via smem
#pragma unroll
    for (int off = 16; off > 0; off >>= 1)
        tsum += __shfl_xor_sync(0xffffffffu, tsum, off);
    int wid = threadIdx.x >> 5;
    int lid = threadIdx.x & 31;
    if (lid == 0) red[wid] = tsum;
    __syncthreads();
    if (threadIdx.x == 0) {
        float tot = red[0];
#pragma unroll
        for (int w = 1; w < BLOCK / 32; w++) tot += red[w];
        g_part[pidx] = (double)wgt * (double)tot;
    }
}

__global__ void reduce_kernel(float* __restrict__ out, int n, float invB)
{
    __shared__ double rd[256];
    double s = 0.0;
    for (int i = threadIdx.x; i < n; i += 256) s += g_part[i];
    rd[threadIdx.x] = s;
    __syncthreads();
#pragma unroll
    for (int s2 = 128; s2 > 0; s2 >>= 1) {
        if (threadIdx.x < s2) rd[threadIdx.x] += rd[threadIdx.x + s2];
        __syncthreads();
    }
    if (threadIdx.x == 0) out[0] = (float)(rd[0] * (double)invB);
}

extern "C" void kernel_launch(void* const* d_in, const int* in_sizes, int n_in,
                              void* d_out, int out_size)
{
    const float* pred  = (const float*)d_in[0];
    const float* targ  = (const float*)d_in[1];
    const int*   faces = (const int*)d_in[2];

    int NV = NV_CONST;
    int B  = in_sizes[0] / (NV * 3);
    int NF = in_sizes[2] / 3;
    int NFP = ((NF + TI - 1) / TI) * TI;   // multiple of 384
    if (NFP > NFP_MAX) NFP = NFP_MAX;
    if (B > SMAX / 2) B = SMAX / 2;

    int prep_total = 2 * B * NFP;
    prep_kernel<<<(prep_total + 255) / 256, 256>>>(pred, targ, faces, B, NV, NF, NFP);

    int gx = NFP / TI;   // 26
    int gy = NFP / TJ;   // 26
    dim3 grid(gx, gy, 3 * B);
    pair_kernel<<<grid, BLOCK>>>(B, NFP, gx, gy);

    int nparts = gx * gy * 3 * B;
    reduce_kernel<<<1, 256>>>((float*)d_out, nparts, 1.0f / (float)B);
}

// round 11
// speedup vs baseline: 1.6271x; 1.6271x over previous
#include <cuda_runtime.h>
#include <cuda_bf16.h>

// Varifold loss on GB300 — factored Gaussian, packed-j f32x2, minimal padding (NFP=9984), g-trick.
// loss = (1/B) * sum_b [ K(s,s) + K(t,t) - 2 K(s,t) ]
// Factorization:
//   M' = sqrt(L) * Nn * exp(-|c'|^2 / 2)   with c' = C / sigma
//   cs = c' * sqrt(log2(e))                so pc = <cs_i,cs_j>
//   g  = <M'_i,M'_j> * 2^pc ;  term_ij = g^2   (exact: g^2 = dm^2 * e^{2<c'_i,c'_j>})

#define NV_CONST 5023
#define TI 384           // i-points per block (128 threads x 3)
#define TJ 384           // j-points per smem tile
#define BLOCK 128
#define NI 3
#define NFP_MAX 9984     // 26 * 384 — only 8 rows of padding over NF=9976
#define SMAX 8
#define PART_MAX 16384

__device__ float4 g_A[SMAX * NFP_MAX];   // (cs.x, cs.y, cs.z, M'.x)
__device__ float4 g_Bv[SMAX * NFP_MAX];  // (M'.y, M'.z, 0, 0)
__device__ double g_part[PART_MAX];

typedef unsigned long long ull;

__device__ __forceinline__ ull pk(float a, float b) {
    ull r; asm("mov.b64 %0, {%1,%2};" : "=l"(r) : "f"(a), "f"(b)); return r;
}
__device__ __forceinline__ void upk(ull v, float& a, float& b) {
    asm("mov.b64 {%0,%1}, %2;" : "=f"(a), "=f"(b) : "l"(v));
}
__device__ __forceinline__ ull f2mul(ull a, ull b) {
    ull r; asm("mul.rn.f32x2 %0, %1, %2;" : "=l"(r) : "l"(a), "l"(b)); return r;
}
__device__ __forceinline__ ull f2fma(ull a, ull b, ull c) {
    ull r; asm("fma.rn.f32x2 %0, %1, %2, %3;" : "=l"(r) : "l"(a), "l"(b), "l"(c)); return r;
}
__device__ __forceinline__ float ex2(float x) {
    float r; asm("ex2.approx.f32 %0, %1;" : "=f"(r) : "f"(x)); return r;
}

__global__ void prep_kernel(const float* __restrict__ pred,
                            const float* __restrict__ targ,
                            const int* __restrict__ faces,
                            int B, int NV, int NF, int NFP)
{
    int idx = blockIdx.x * blockDim.x + threadIdx.x;
    int total = 2 * B * NFP;
    if (idx >= total) return;
    int s = idx / NFP;
    int f = idx - s * NFP;

    float4 A = make_float4(0.f, 0.f, 0.f, 0.f);
    float4 Bv = make_float4(0.f, 0.f, 0.f, 0.f);

    if (f < NF) {
        const float* src = (s < B) ? pred : targ;
        int b = (s < B) ? s : (s - B);
        const float* base = src + (size_t)b * NV * 3;

        int i0 = faces[3 * f + 0];
        int i1 = faces[3 * f + 1];
        int i2 = faces[3 * f + 2];

        float x0 = base[3 * i0 + 0], y0 = base[3 * i0 + 1], z0 = base[3 * i0 + 2];
        float x1 = base[3 * i1 + 0], y1 = base[3 * i1 + 1], z1 = base[3 * i1 + 2];
        float x2 = base[3 * i2 + 0], y2 = base[3 * i2 + 1], z2 = base[3 * i2 + 2];

        // c' = centroid / sigma  (sigma = 0.03)
        const float SG = 33.333333333333336f;
        float cx = (x0 + x1 + x2) * (1.0f / 3.0f) * SG;
        float cy = (y0 + y1 + y2) * (1.0f / 3.0f) * SG;
        float cz = (z0 + z1 + z2) * (1.0f / 3.0f) * SG;

        float e1x = x1 - x0, e1y = y1 - y0, e1z = z1 - z0;
        float e2x = x2 - x0, e2y = y2 - y0, e2z = z2 - z0;

        float nx = 0.5f * (e1y * e2z - e1z * e2y);
        float ny = 0.5f * (e1z * e2x - e1x * e2z);
        float nz = 0.5f * (e1x * e2y - e1y * e2x);

        float L = sqrtf(nx * nx + ny * ny + nz * nz);
        float w = expf(-0.5f * (cx * cx + cy * cy + cz * cz));
        float sc = (sqrtf(L) / fmaxf(L, 1e-12f)) * w;
        float mx = nx * sc, my = ny * sc, mz = nz * sc;

        const float SQLE = 1.2011224087864498f;  // sqrt(log2(e))
        A = make_float4(cx * SQLE, cy * SQLE, cz * SQLE, mx);
        Bv = make_float4(my, mz, 0.f, 0.f);
    }
    g_A[(size_t)s * NFP + f] = A;
    g_Bv[(size_t)s * NFP + f] = Bv;
}

__global__ void __launch_bounds__(BLOCK, 5)
pair_kernel(int B, int NFP, int gx, int gy)
{
    // SoA j-tile: packed pairs of consecutive j-points load as one ld.shared.b64.
    __shared__ float s_x[TJ], s_y[TJ], s_z[TJ];
    __shared__ float s_mx[TJ], s_my[TJ], s_mz[TJ];
    __shared__ float red[BLOCK / 32];

    int z = blockIdx.z;
    int b = z / 3;
    int t = z - 3 * b;           // 0: ss, 1: tt, 2: st
    int pidx = (z * gy + blockIdx.y) * gx + blockIdx.x;

    float wgt = (t == 2) ? -2.f : 1.f;
    if (t < 2) {
        // symmetric kernel, TI == TJ: square tiles, strict triangle
        int jt = blockIdx.y, it = blockIdx.x;
        if (jt < it) {                    // strictly lower: skip
            if (threadIdx.x == 0) g_part[pidx] = 0.0;
            return;
        }
        if (jt > it) wgt = 2.f;           // strictly upper: count twice
    }

    int sx = (t == 1) ? (B + b) : b;
    int sy = (t == 0) ? b : (B + b);

    const float4* __restrict__ XA = g_A  + (size_t)sx * NFP;
    const float4* __restrict__ XB = g_Bv + (size_t)sx * NFP;
    const float4* __restrict__ YA = g_A  + (size_t)sy * NFP;
    const float4* __restrict__ YB = g_Bv + (size_t)sy * NFP;

    // Load NI i-points, duplicate each component {v,v} ONCE (hoisted out of j-loop)
    int i0 = blockIdx.x * TI + threadIdx.x;
    ull icx[NI], icy[NI], icz[NI], imx[NI], imy[NI], imz[NI];
#pragma unroll
    for (int k = 0; k < NI; k++) {
        float4 a = XA[i0 + k * BLOCK];
        float4 v = XB[i0 + k * BLOCK];
        icx[k] = pk(a.x, a.x);
        icy[k] = pk(a.y, a.y);
        icz[k] = pk(a.z, a.z);
        imx[k] = pk(a.w, a.w);
        imy[k] = pk(v.x, v.x);
        imz[k] = pk(v.y, v.y);
    }

    int j0 = blockIdx.y * TJ;
#pragma unroll
    for (int r = 0; r < TJ / BLOCK; r++) {
        int jj = threadIdx.x + r * BLOCK;
        float4 a = YA[j0 + jj];
        float4 v = YB[j0 + jj];
        s_x[jj] = a.x;  s_y[jj] = a.y;  s_z[jj] = a.z;
        s_mx[jj] = a.w; s_my[jj] = v.x; s_mz[jj] = v.y;
    }
    __syncthreads();

    const ull* __restrict__ px  = (const ull*)s_x;
    const ull* __restrict__ py  = (const ull*)s_y;
    const ull* __restrict__ pz  = (const ull*)s_z;
    const ull* __restrict__ pmx = (const ull*)s_mx;
    const ull* __restrict__ pmy = (const ull*)s_my;
    const ull* __restrict__ pmz = (const ull*)s_mz;

    ull acc[NI];
#pragma unroll
    for (int k = 0; k < NI; k++) acc[k] = 0ull;   // (0.0f, 0.0f)

#pragma unroll 4
    for (int j2 = 0; j2 < TJ / 2; j2++) {
        ull jx  = px[j2];
        ull jy  = py[j2];
        ull jz  = pz[j2];
        ull jmx = pmx[j2];
        ull jmy = pmy[j2];
        ull jmz = pmz[j2];
#pragma unroll
        for (int k = 0; k < NI; k++) {
            ull pc = f2fma(jz, icz[k], f2fma(jy, icy[k], f2mul(jx, icx[k])));
            ull dm = f2fma(jmz, imz[k], f2fma(jmy, imy[k], f2mul(jmx, imx[k])));
            float p0, p1; upk(pc, p0, p1);
            float e0 = ex2(p0);
            float e1 = ex2(p1);
            ull g = f2mul(dm, pk(e0, e1));   // rt2
            acc[k] = f2fma(g, g, acc[k]);    // rt2 (even/odd operand dedup)
        }
    }

    float tsum = 0.f;
#pragma unroll
    for (int k = 0; k < NI; k++) {
        float a0, a1; upk(acc[k], a0, a1);
        tsum += a0 + a1;
    }
    // warp shuffle reduction, then cross-warp via smem
#pragma unroll
    for (int off = 16; off > 0; off >>= 1)
        tsum += __shfl_xor_sync(0xffffffffu, tsum, off);
    int wid = threadIdx.x >> 5;
    int lid = threadIdx.x & 31;
    if (lid == 0) red[wid] = tsum;
    __syncthreads();
    if (threadIdx.x == 0) {
        float tot = red[0];
#pragma unroll
        for (int w = 1; w < BLOCK / 32; w++) tot += red[w];
        g_part[pidx] = (double)wgt * (double)tot;
    }
}

__global__ void reduce_kernel(float* __restrict__ out, int n, float invB)
{
    __shared__ double rd[256];
    double s = 0.0;
    for (int i = threadIdx.x; i < n; i += 256) s += g_part[i];
    rd[threadIdx.x] = s;
    __syncthreads();
#pragma unroll
    for (int s2 = 128; s2 > 0; s2 >>= 1) {
        if (threadIdx.x < s2) rd[threadIdx.x] += rd[threadIdx.x + s2];
        __syncthreads();
    }
    if (threadIdx.x == 0) out[0] = (float)(rd[0] * (double)invB);
}

extern "C" void kernel_launch(void* const* d_in, const int* in_sizes, int n_in,
                              void* d_out, int out_size)
{
    const float* pred  = (const float*)d_in[0];
    const float* targ  = (const float*)d_in[1];
    const int*   faces = (const int*)d_in[2];

    int NV = NV_CONST;
    int B  = in_sizes[0] / (NV * 3);
    int NF = in_sizes[2] / 3;
    int NFP = ((NF + TI - 1) / TI) * TI;   // multiple of 384
    if (NFP > NFP_MAX) NFP = NFP_MAX;
    if (B > SMAX / 2) B = SMAX / 2;

    int prep_total = 2 * B * NFP;
    prep_kernel<<<(prep_total + 255) / 256, 256>>>(pred, targ, faces, B, NV, NF, NFP);

    int gx = NFP / TI;   // 26
    int gy = NFP / TJ;   // 26
    dim3 grid(gx, gy, 3 * B);
    pair_kernel<<<grid, BLOCK>>>(B, NFP, gx, gy);

    int nparts = gx * gy * 3 * B;
    reduce_kernel<<<1, 256>>>((float*)d_out, nparts, 1.0f / (float)B);
}